// round 6
// baseline (speedup 1.0000x reference)
#include <cuda_runtime.h>
#include <math.h>
#include <stdint.h>

#define NN 100000
#define NE 1600000
#define NEG_SLOPE 0.2f

// ---------------- scratch (device globals; no allocations allowed) ----------
__device__ float g_bufA[(size_t)NN * 256];
__device__ float g_bufB[(size_t)NN * 256];
__device__ float g_es[NN * 4];
__device__ float g_ed[NN * 4];
__device__ float g_ex[(size_t)NE * 4];       // per-edge exp numerators (CSR order)
__device__ int   g_deg[NN];
__device__ int   g_off[NN + 1];
__device__ int   g_cursor[NN];
__device__ int   g_adj[NE];                  // src node per CSR slot
__device__ int   g_pos[NE];                  // original edge -> CSR slot

// ---------------- CSR build --------------------------------------------------
__global__ void count_deg(const int* __restrict__ dst, int* __restrict__ deg) {
    int e = blockIdx.x * blockDim.x + threadIdx.x;
    if (e < NE) atomicAdd(&deg[dst[e]], 1);
}

__global__ void scan_offsets(const int* __restrict__ deg,
                             int* __restrict__ off, int* __restrict__ cursor) {
    __shared__ int s[1024];
    const int tid = threadIdx.x;
    const int CH = (NN + 1023) / 1024;
    const int b0 = tid * CH;
    int sum = 0;
    for (int i = 0; i < CH; i++) {
        int idx = b0 + i;
        if (idx < NN) sum += deg[idx];
    }
    s[tid] = sum;
    __syncthreads();
    for (int o = 1; o < 1024; o <<= 1) {
        int t = (tid >= o) ? s[tid - o] : 0;
        __syncthreads();
        s[tid] += t;
        __syncthreads();
    }
    int run = s[tid] - sum;
    for (int i = 0; i < CH; i++) {
        int idx = b0 + i;
        if (idx < NN) {
            off[idx] = run;
            cursor[idx] = run;
            run += deg[idx];
        }
    }
    if (tid == 0) off[NN] = NE;
}

__global__ void fill_adj(const int* __restrict__ src, const int* __restrict__ dst,
                         int* __restrict__ cursor, int* __restrict__ adj,
                         int* __restrict__ pos) {
    int e = blockIdx.x * blockDim.x + threadIdx.x;
    if (e < NE) {
        int d = dst[e];
        int p = atomicAdd(&cursor[d], 1);
        adj[p] = src[e];
        pos[e] = p;
    }
}

// ---------------- tf32 / async helpers ---------------------------------------
__device__ __forceinline__ uint32_t f2tf32(float f) {
    uint32_t r;
    asm("cvt.rna.tf32.f32 %0, %1;" : "=r"(r) : "f"(f));
    return r;
}

__device__ __forceinline__ void mma_tf32(float* d, const uint32_t* a, const uint32_t* b) {
    asm volatile(
        "mma.sync.aligned.m16n8k8.row.col.f32.tf32.tf32.f32 "
        "{%0,%1,%2,%3}, {%4,%5,%6,%7}, {%8,%9}, {%0,%1,%2,%3};"
        : "+f"(d[0]), "+f"(d[1]), "+f"(d[2]), "+f"(d[3])
        : "r"(a[0]), "r"(a[1]), "r"(a[2]), "r"(a[3]), "r"(b[0]), "r"(b[1]));
}

__device__ __forceinline__ void cp_async16(void* smem, const void* g, bool pred) {
    uint32_t s = (uint32_t)__cvta_generic_to_shared(smem);
    int sz = pred ? 16 : 0;
    asm volatile("cp.async.cg.shared.global [%0], [%1], 16, %2;"
                 :: "r"(s), "l"(g), "r"(sz));
}

// ---------------- tf32 tensor-core GEMM with cp.async double buffering -------
#define A_PITCH 36
#define B_PITCH 136
#define A_WORDS (128 * A_PITCH)
#define B_WORDS (32 * B_PITCH)
#define GEMM_SMEM ((2 * (A_WORDS + B_WORDS)) * 4)

__global__ void __launch_bounds__(256, 2) gemm_tf32(
    const float* __restrict__ A, const float* __restrict__ B,
    float* __restrict__ C, int M, int N, int K)
{
    extern __shared__ float smem[];
    float* Asm = smem;
    float* Bsm = smem + 2 * A_WORDS;

    const int bm = blockIdx.y * 128;
    const int bn = blockIdx.x * 128;
    const int tid = threadIdx.x;
    const int lane = tid & 31;
    const int wid = tid >> 5;
    const int wm = (wid >> 2) * 64;
    const int wn = (wid & 3) * 32;
    const int gid = lane >> 2;
    const int tig = lane & 3;

    float acc[4][4][4];
    #pragma unroll
    for (int i = 0; i < 4; i++)
        #pragma unroll
        for (int j = 0; j < 4; j++)
            #pragma unroll
            for (int k = 0; k < 4; k++) acc[i][j][k] = 0.0f;

    auto stage = [&](int ss, int k0) {
        float* As = Asm + ss * A_WORDS;
        float* Bs = Bsm + ss * B_WORDS;
        #pragma unroll
        for (int i = 0; i < 4; i++) {
            int idx = tid + 256 * i;
            int row = idx >> 3;
            int kq  = (idx & 7) * 4;
            int gr = bm + row;
            bool ok = gr < M;
            const float* srcp = A + (size_t)(ok ? gr : (M - 1)) * K + k0 + kq;
            cp_async16(As + row * A_PITCH + kq, srcp, ok);
        }
        #pragma unroll
        for (int i = 0; i < 4; i++) {
            int idx = tid + 256 * i;
            int kr = idx >> 5;
            int nq = (idx & 31) * 4;
            int gc = bn + nq;
            bool ok = gc + 4 <= N;
            const float* srcp = B + (size_t)(k0 + kr) * N + (ok ? gc : (N - 4));
            cp_async16(Bs + kr * B_PITCH + nq, srcp, ok);
        }
        asm volatile("cp.async.commit_group;");
    };

    const int nk = K >> 5;
    stage(0, 0);

    for (int it = 0; it < nk; it++) {
        const int cur = it & 1;
        if (it + 1 < nk) {
            stage(cur ^ 1, (it + 1) * 32);
            asm volatile("cp.async.wait_group 1;");
        } else {
            asm volatile("cp.async.wait_group 0;");
        }
        __syncthreads();

        const float* As = Asm + cur * A_WORDS;
        const float* Bs = Bsm + cur * B_WORDS;
        #pragma unroll
        for (int ks = 0; ks < 4; ks++) {
            const int kk = ks * 8 + tig;
            uint32_t a[4][4], b[4][2];
            #pragma unroll
            for (int mt = 0; mt < 4; mt++) {
                int m0 = wm + mt * 16 + gid;
                a[mt][0] = f2tf32(As[m0 * A_PITCH + kk]);
                a[mt][1] = f2tf32(As[(m0 + 8) * A_PITCH + kk]);
                a[mt][2] = f2tf32(As[m0 * A_PITCH + kk + 4]);
                a[mt][3] = f2tf32(As[(m0 + 8) * A_PITCH + kk + 4]);
            }
            #pragma unroll
            for (int nt = 0; nt < 4; nt++) {
                int n0 = wn + nt * 8 + gid;
                b[nt][0] = f2tf32(Bs[kk * B_PITCH + n0]);
                b[nt][1] = f2tf32(Bs[(kk + 4) * B_PITCH + n0]);
            }
            #pragma unroll
            for (int mt = 0; mt < 4; mt++)
                #pragma unroll
                for (int nt = 0; nt < 4; nt++)
                    mma_tf32(acc[mt][nt], a[mt], b[nt]);
        }
        __syncthreads();
    }

    #pragma unroll
    for (int mt = 0; mt < 4; mt++) {
        int r0 = bm + wm + mt * 16 + gid;
        #pragma unroll
        for (int nt = 0; nt < 4; nt++) {
            int c0 = bn + wn + nt * 8 + 2 * tig;
            if (c0 < N) {
                if (r0 < M)
                    *reinterpret_cast<float2*>(C + (size_t)r0 * N + c0) =
                        make_float2(acc[mt][nt][0], acc[mt][nt][1]);
                if (r0 + 8 < M)
                    *reinterpret_cast<float2*>(C + (size_t)(r0 + 8) * N + c0) =
                        make_float2(acc[mt][nt][2], acc[mt][nt][3]);
            }
        }
    }
}

// ---------------- attention coefficients (coalesced) -------------------------
template<int H>
__global__ void attn_coef(const float* __restrict__ hfeat,
                          const float* __restrict__ a_src,
                          const float* __restrict__ a_dst,
                          float* __restrict__ es, float* __restrict__ ed)
{
    const int ROWS = NN * H;
    int gw = blockIdx.x * 8 + (threadIdx.x >> 5);
    int lane = threadIdx.x & 31;
    int r = lane >> 2;            // 0..7
    int q = lane & 3;             // 0..3
    int row = gw * 8 + r;
    if (row >= ROWS) return;
    int head = row % H;

    const float* hp  = hfeat + (size_t)row * 64 + q * 16;
    const float* asp = a_src + head * 64 + q * 16;
    const float* adp = a_dst + head * 64 + q * 16;
    float s1 = 0.0f, s2 = 0.0f;
    #pragma unroll
    for (int j = 0; j < 16; j += 4) {
        float4 hv = *reinterpret_cast<const float4*>(hp + j);
        float4 av = *reinterpret_cast<const float4*>(asp + j);
        float4 dv = *reinterpret_cast<const float4*>(adp + j);
        s1 += hv.x * av.x + hv.y * av.y + hv.z * av.z + hv.w * av.w;
        s2 += hv.x * dv.x + hv.y * dv.y + hv.z * dv.z + hv.w * dv.w;
    }
    s1 += __shfl_xor_sync(0xffffffff, s1, 1);
    s2 += __shfl_xor_sync(0xffffffff, s2, 1);
    s1 += __shfl_xor_sync(0xffffffff, s1, 2);
    s2 += __shfl_xor_sync(0xffffffff, s2, 2);
    if (q == 0) {
        es[row] = s1;
        ed[row] = s2;
    }
}

// ---------------- per-edge exp numerators, scattered to CSR slot order -------
template<int H>
__global__ void edge_exp(const int* __restrict__ src, const int* __restrict__ dst,
                         const int* __restrict__ pos,
                         const float* __restrict__ es, const float* __restrict__ ed,
                         float* __restrict__ ex)
{
    int e = blockIdx.x * blockDim.x + threadIdx.x;
    if (e >= NE) return;
    int s = src[e], d = dst[e];
    int p = pos[e];
    if constexpr (H == 4) {
        float4 a = *reinterpret_cast<const float4*>(es + s * 4);
        float4 b = *reinterpret_cast<const float4*>(ed + d * 4);
        float v0 = a.x + b.x, v1 = a.y + b.y, v2 = a.z + b.z, v3 = a.w + b.w;
        v0 = (v0 > 0.0f) ? v0 : NEG_SLOPE * v0;
        v1 = (v1 > 0.0f) ? v1 : NEG_SLOPE * v1;
        v2 = (v2 > 0.0f) ? v2 : NEG_SLOPE * v2;
        v3 = (v3 > 0.0f) ? v3 : NEG_SLOPE * v3;
        *reinterpret_cast<float4*>(ex + (size_t)p * 4) =
            make_float4(__expf(v0), __expf(v1), __expf(v2), __expf(v3));
    } else {
        float v = es[s] + ed[d];
        v = (v > 0.0f) ? v : NEG_SLOPE * v;
        ex[p] = __expf(v);
    }
}

// ---------------- fused aggregation ------------------------------------------
// WPN warps per destination node; ex (CSR order) read sequentially.
// Edge loop unrolled x4 for memory-level parallelism.
template<int H, int WPN, bool ELU>
__global__ void __launch_bounds__(256) node_aggr(
    const int* __restrict__ off, const int* __restrict__ adj,
    const float* __restrict__ ex, const float* __restrict__ hfeat,
    const float* __restrict__ bias, float* __restrict__ out)
{
    constexpr int HD  = H * 64;
    constexpr int PER = HD / (32 * WPN);     // 4 (H=4,WPN=2) or 2 (H=1,WPN=1)
    int gw = blockIdx.x * 8 + (threadIdx.x >> 5);
    int node = gw / WPN;
    int sub  = gw % WPN;
    if (node >= NN) return;
    int lane = threadIdx.x & 31;
    int base = sub * (HD / WPN) + lane * PER;
    int head = base >> 6;

    int e0 = off[node], e1 = off[node + 1];

    float acc[PER];
    #pragma unroll
    for (int j = 0; j < PER; j++) acc[j] = 0.0f;
    float denom = 0.0f;

    int e = e0;
    for (; e + 4 <= e1; e += 4) {
        int s0 = adj[e],     s1 = adj[e + 1];
        int s2 = adj[e + 2], s3 = adj[e + 3];
        float x0 = ex[(size_t)(e)     * H + head];
        float x1 = ex[(size_t)(e + 1) * H + head];
        float x2 = ex[(size_t)(e + 2) * H + head];
        float x3 = ex[(size_t)(e + 3) * H + head];
        denom += (x0 + x1) + (x2 + x3);
        const float* h0 = hfeat + (size_t)s0 * HD + base;
        const float* h1 = hfeat + (size_t)s1 * HD + base;
        const float* h2 = hfeat + (size_t)s2 * HD + base;
        const float* h3 = hfeat + (size_t)s3 * HD + base;
        if constexpr (PER == 4) {
            float4 f0 = *reinterpret_cast<const float4*>(h0);
            float4 f1 = *reinterpret_cast<const float4*>(h1);
            float4 f2 = *reinterpret_cast<const float4*>(h2);
            float4 f3 = *reinterpret_cast<const float4*>(h3);
            acc[0] += x0 * f0.x + x1 * f1.x + x2 * f2.x + x3 * f3.x;
            acc[1] += x0 * f0.y + x1 * f1.y + x2 * f2.y + x3 * f3.y;
            acc[2] += x0 * f0.z + x1 * f1.z + x2 * f2.z + x3 * f3.z;
            acc[3] += x0 * f0.w + x1 * f1.w + x2 * f2.w + x3 * f3.w;
        } else {
            float2 f0 = *reinterpret_cast<const float2*>(h0);
            float2 f1 = *reinterpret_cast<const float2*>(h1);
            float2 f2 = *reinterpret_cast<const float2*>(h2);
            float2 f3 = *reinterpret_cast<const float2*>(h3);
            acc[0] += x0 * f0.x + x1 * f1.x + x2 * f2.x + x3 * f3.x;
            acc[1] += x0 * f0.y + x1 * f1.y + x2 * f2.y + x3 * f3.y;
        }
    }
    for (; e < e1; e++) {
        int s0 = adj[e];
        float x0 = ex[(size_t)e * H + head];
        denom += x0;
        const float* h0 = hfeat + (size_t)s0 * HD + base;
        if constexpr (PER == 4) {
            float4 f0 = *reinterpret_cast<const float4*>(h0);
            acc[0] += x0 * f0.x; acc[1] += x0 * f0.y;
            acc[2] += x0 * f0.z; acc[3] += x0 * f0.w;
        } else {
            float2 f0 = *reinterpret_cast<const float2*>(h0);
            acc[0] += x0 * f0.x; acc[1] += x0 * f0.y;
        }
    }

    float inv = 1.0f / (denom + 1e-16f);
    float* op = out + (size_t)node * HD + base;
    float res[PER];
    #pragma unroll
    for (int j = 0; j < PER; j++) {
        float r = acc[j] * inv + bias[base + j];
        if (ELU) r = (r > 0.0f) ? r : expm1f(r);
        res[j] = r;
    }
    if constexpr (PER == 4) {
        *reinterpret_cast<float4*>(op) = make_float4(res[0], res[1], res[2], res[3]);
    } else {
        *reinterpret_cast<float2*>(op) = make_float2(res[0], res[1]);
    }
}

// ---------------- driver -----------------------------------------------------
extern "C" void kernel_launch(void* const* d_in, const int* in_sizes, int n_in,
                              void* d_out, int out_size)
{
    const float* x   = (const float*)d_in[0];
    const int*   ei  = (const int*)  d_in[1];
    const int*   src = ei;
    const int*   dst = ei + NE;
    const float* W1  = (const float*)d_in[2];
    const float* as1 = (const float*)d_in[3];
    const float* ad1 = (const float*)d_in[4];
    const float* b1  = (const float*)d_in[5];
    const float* W2  = (const float*)d_in[6];
    const float* as2 = (const float*)d_in[7];
    const float* ad2 = (const float*)d_in[8];
    const float* b2  = (const float*)d_in[9];
    const float* W3  = (const float*)d_in[10];
    const float* as3 = (const float*)d_in[11];
    const float* ad3 = (const float*)d_in[12];
    const float* b3  = (const float*)d_in[13];

    float *bufA, *bufB, *es, *ed, *ex;
    int *deg, *off, *cursor, *adj, *pos;
    cudaGetSymbolAddress((void**)&bufA, g_bufA);
    cudaGetSymbolAddress((void**)&bufB, g_bufB);
    cudaGetSymbolAddress((void**)&es,   g_es);
    cudaGetSymbolAddress((void**)&ed,   g_ed);
    cudaGetSymbolAddress((void**)&ex,   g_ex);
    cudaGetSymbolAddress((void**)&deg,    g_deg);
    cudaGetSymbolAddress((void**)&off,    g_off);
    cudaGetSymbolAddress((void**)&cursor, g_cursor);
    cudaGetSymbolAddress((void**)&adj,    g_adj);
    cudaGetSymbolAddress((void**)&pos,    g_pos);

    static bool attr_set = false;
    if (!attr_set) {
        cudaFuncSetAttribute(gemm_tf32,
                             cudaFuncAttributeMaxDynamicSharedMemorySize, GEMM_SMEM);
        attr_set = true;
    }

    const int TB = 256;
    const int eblk  = (NE + TB - 1) / TB;
    const int mblk  = (NN + 127) / 128;
    const int nblk4 = (NN * 2 + 7) / 8;        // H=4: 2 warps per node
    const int nblk1 = (NN + 7) / 8;            // H=1: 1 warp per node
    const int awrp4 = ((NN * 4 + 7) / 8 + 7) / 8;
    const int awrp1 = ((NN + 7) / 8 + 7) / 8;

    // ---- CSR build (once, reused by all 3 layers) ----
    cudaMemsetAsync(deg, 0, NN * sizeof(int));
    count_deg<<<eblk, TB>>>(dst, deg);
    scan_offsets<<<1, 1024>>>(deg, off, cursor);
    fill_adj<<<eblk, TB>>>(src, dst, cursor, adj, pos);

    // ---- layer 1 (H=4) ----
    gemm_tf32<<<dim3(2, mblk), TB, GEMM_SMEM>>>(x, W1, bufA, NN, 256, 256);
    attn_coef<4><<<awrp4, TB>>>(bufA, as1, ad1, es, ed);
    edge_exp<4><<<eblk, TB>>>(src, dst, pos, es, ed, ex);
    node_aggr<4, 2, true><<<nblk4, TB>>>(off, adj, ex, bufA, b1, bufB);

    // ---- layer 2 (H=4) ----
    gemm_tf32<<<dim3(2, mblk), TB, GEMM_SMEM>>>(bufB, W2, bufA, NN, 256, 256);
    attn_coef<4><<<awrp4, TB>>>(bufA, as2, ad2, es, ed);
    edge_exp<4><<<eblk, TB>>>(src, dst, pos, es, ed, ex);
    node_aggr<4, 2, true><<<nblk4, TB>>>(off, adj, ex, bufA, b2, bufB);

    // ---- layer 3 (H=1) ----
    float* outp = (float*)d_out;
    gemm_tf32<<<dim3(1, mblk), TB, GEMM_SMEM>>>(bufB, W3, bufA, NN, 64, 256);
    attn_coef<1><<<awrp1, TB>>>(bufA, as3, ad3, es, ed);
    edge_exp<1><<<eblk, TB>>>(src, dst, pos, es, ed, ex);
    node_aggr<1, 1, false><<<nblk1, TB>>>(off, adj, ex, bufA, b3, outp);
}

// round 8
// speedup vs baseline: 1.2528x; 1.2528x over previous
#include <cuda_runtime.h>
#include <cuda_fp16.h>
#include <math.h>
#include <stdint.h>

#define NN 100000
#define NE 1600000
#define NEG_SLOPE 0.2f

// ---------------- scratch (device globals; no allocations allowed) ----------
__device__ float  g_bufA[(size_t)NN * 256];    // h (fp32, for attn + next GEMM)
__device__ float  g_bufB[(size_t)NN * 256];    // aggregated output / next input
__device__ __half g_bufH[(size_t)NN * 256];    // h (fp16 copy, for gathers)
__device__ float  g_es[NN * 4];
__device__ float  g_ed[NN * 4];
__device__ int    g_deg[NN];
__device__ int    g_off[NN + 1];
__device__ int    g_cursor[NN];
__device__ int    g_adj[NE];

// ---------------- CSR build --------------------------------------------------
__global__ void count_deg(const int* __restrict__ dst, int* __restrict__ deg) {
    int e = blockIdx.x * blockDim.x + threadIdx.x;
    if (e < NE) atomicAdd(&deg[dst[e]], 1);
}

__global__ void scan_offsets(const int* __restrict__ deg,
                             int* __restrict__ off, int* __restrict__ cursor) {
    __shared__ int s[1024];
    const int tid = threadIdx.x;
    const int CH = (NN + 1023) / 1024;
    const int b0 = tid * CH;
    int sum = 0;
    for (int i = 0; i < CH; i++) {
        int idx = b0 + i;
        if (idx < NN) sum += deg[idx];
    }
    s[tid] = sum;
    __syncthreads();
    for (int o = 1; o < 1024; o <<= 1) {
        int t = (tid >= o) ? s[tid - o] : 0;
        __syncthreads();
        s[tid] += t;
        __syncthreads();
    }
    int run = s[tid] - sum;
    for (int i = 0; i < CH; i++) {
        int idx = b0 + i;
        if (idx < NN) {
            off[idx] = run;
            cursor[idx] = run;
            run += deg[idx];
        }
    }
    if (tid == 0) off[NN] = NE;
}

__global__ void fill_adj(const int* __restrict__ src, const int* __restrict__ dst,
                         int* __restrict__ cursor, int* __restrict__ adj) {
    int e = blockIdx.x * blockDim.x + threadIdx.x;
    if (e < NE) {
        int d = dst[e];
        int p = atomicAdd(&cursor[d], 1);
        adj[p] = src[e];
    }
}

// ---------------- tf32 / async helpers ---------------------------------------
__device__ __forceinline__ uint32_t f2tf32(float f) {
    uint32_t r;
    asm("cvt.rna.tf32.f32 %0, %1;" : "=r"(r) : "f"(f));
    return r;
}

__device__ __forceinline__ void mma_tf32(float* d, const uint32_t* a, const uint32_t* b) {
    asm volatile(
        "mma.sync.aligned.m16n8k8.row.col.f32.tf32.tf32.f32 "
        "{%0,%1,%2,%3}, {%4,%5,%6,%7}, {%8,%9}, {%0,%1,%2,%3};"
        : "+f"(d[0]), "+f"(d[1]), "+f"(d[2]), "+f"(d[3])
        : "r"(a[0]), "r"(a[1]), "r"(a[2]), "r"(a[3]), "r"(b[0]), "r"(b[1]));
}

__device__ __forceinline__ void cp_async16(void* smem, const void* g, bool pred) {
    uint32_t s = (uint32_t)__cvta_generic_to_shared(smem);
    int sz = pred ? 16 : 0;
    asm volatile("cp.async.cg.shared.global [%0], [%1], 16, %2;"
                 :: "r"(s), "l"(g), "r"(sz));
}

// ---------------- tf32 tensor-core GEMM, dual fp32+fp16 output ---------------
#define A_PITCH 36
#define B_PITCH 136
#define A_WORDS (128 * A_PITCH)
#define B_WORDS (32 * B_PITCH)
#define GEMM_SMEM ((2 * (A_WORDS + B_WORDS)) * 4)

__global__ void __launch_bounds__(256, 2) gemm_tf32(
    const float* __restrict__ A, const float* __restrict__ B,
    float* __restrict__ C, __half* __restrict__ Ch, int M, int N, int K)
{
    extern __shared__ float smem[];
    float* Asm = smem;
    float* Bsm = smem + 2 * A_WORDS;

    const int bm = blockIdx.y * 128;
    const int bn = blockIdx.x * 128;
    const int tid = threadIdx.x;
    const int lane = tid & 31;
    const int wid = tid >> 5;
    const int wm = (wid >> 2) * 64;
    const int wn = (wid & 3) * 32;
    const int gid = lane >> 2;
    const int tig = lane & 3;

    float acc[4][4][4];
    #pragma unroll
    for (int i = 0; i < 4; i++)
        #pragma unroll
        for (int j = 0; j < 4; j++)
            #pragma unroll
            for (int k = 0; k < 4; k++) acc[i][j][k] = 0.0f;

    auto stage = [&](int ss, int k0) {
        float* As = Asm + ss * A_WORDS;
        float* Bs = Bsm + ss * B_WORDS;
        #pragma unroll
        for (int i = 0; i < 4; i++) {
            int idx = tid + 256 * i;
            int row = idx >> 3;
            int kq  = (idx & 7) * 4;
            int gr = bm + row;
            bool ok = gr < M;
            const float* srcp = A + (size_t)(ok ? gr : (M - 1)) * K + k0 + kq;
            cp_async16(As + row * A_PITCH + kq, srcp, ok);
        }
        #pragma unroll
        for (int i = 0; i < 4; i++) {
            int idx = tid + 256 * i;
            int kr = idx >> 5;
            int nq = (idx & 31) * 4;
            int gc = bn + nq;
            bool ok = gc + 4 <= N;
            const float* srcp = B + (size_t)(k0 + kr) * N + (ok ? gc : (N - 4));
            cp_async16(Bs + kr * B_PITCH + nq, srcp, ok);
        }
        asm volatile("cp.async.commit_group;");
    };

    const int nk = K >> 5;
    stage(0, 0);

    for (int it = 0; it < nk; it++) {
        const int cur = it & 1;
        if (it + 1 < nk) {
            stage(cur ^ 1, (it + 1) * 32);
            asm volatile("cp.async.wait_group 1;");
        } else {
            asm volatile("cp.async.wait_group 0;");
        }
        __syncthreads();

        const float* As = Asm + cur * A_WORDS;
        const float* Bs = Bsm + cur * B_WORDS;
        #pragma unroll
        for (int ks = 0; ks < 4; ks++) {
            const int kk = ks * 8 + tig;
            uint32_t a[4][4], b[4][2];
            #pragma unroll
            for (int mt = 0; mt < 4; mt++) {
                int m0 = wm + mt * 16 + gid;
                a[mt][0] = f2tf32(As[m0 * A_PITCH + kk]);
                a[mt][1] = f2tf32(As[(m0 + 8) * A_PITCH + kk]);
                a[mt][2] = f2tf32(As[m0 * A_PITCH + kk + 4]);
                a[mt][3] = f2tf32(As[(m0 + 8) * A_PITCH + kk + 4]);
            }
            #pragma unroll
            for (int nt = 0; nt < 4; nt++) {
                int n0 = wn + nt * 8 + gid;
                b[nt][0] = f2tf32(Bs[kk * B_PITCH + n0]);
                b[nt][1] = f2tf32(Bs[(kk + 4) * B_PITCH + n0]);
            }
            #pragma unroll
            for (int mt = 0; mt < 4; mt++)
                #pragma unroll
                for (int nt = 0; nt < 4; nt++)
                    mma_tf32(acc[mt][nt], a[mt], b[nt]);
        }
        __syncthreads();
    }

    #pragma unroll
    for (int mt = 0; mt < 4; mt++) {
        int r0 = bm + wm + mt * 16 + gid;
        #pragma unroll
        for (int nt = 0; nt < 4; nt++) {
            int c0 = bn + wn + nt * 8 + 2 * tig;
            if (c0 < N) {
                if (r0 < M) {
                    *reinterpret_cast<float2*>(C + (size_t)r0 * N + c0) =
                        make_float2(acc[mt][nt][0], acc[mt][nt][1]);
                    *reinterpret_cast<__half2*>(Ch + (size_t)r0 * N + c0) =
                        __floats2half2_rn(acc[mt][nt][0], acc[mt][nt][1]);
                }
                if (r0 + 8 < M) {
                    *reinterpret_cast<float2*>(C + (size_t)(r0 + 8) * N + c0) =
                        make_float2(acc[mt][nt][2], acc[mt][nt][3]);
                    *reinterpret_cast<__half2*>(Ch + (size_t)(r0 + 8) * N + c0) =
                        __floats2half2_rn(acc[mt][nt][2], acc[mt][nt][3]);
                }
            }
        }
    }
}

// ---------------- attention coefficients (coalesced) -------------------------
template<int H>
__global__ void attn_coef(const float* __restrict__ hfeat,
                          const float* __restrict__ a_src,
                          const float* __restrict__ a_dst,
                          float* __restrict__ es, float* __restrict__ ed)
{
    const int ROWS = NN * H;
    int gw = blockIdx.x * 8 + (threadIdx.x >> 5);
    int lane = threadIdx.x & 31;
    int r = lane >> 2;
    int q = lane & 3;
    int row = gw * 8 + r;
    if (row >= ROWS) return;
    int head = row % H;

    const float* hp  = hfeat + (size_t)row * 64 + q * 16;
    const float* asp = a_src + head * 64 + q * 16;
    const float* adp = a_dst + head * 64 + q * 16;
    float s1 = 0.0f, s2 = 0.0f;
    #pragma unroll
    for (int j = 0; j < 16; j += 4) {
        float4 hv = *reinterpret_cast<const float4*>(hp + j);
        float4 av = *reinterpret_cast<const float4*>(asp + j);
        float4 dv = *reinterpret_cast<const float4*>(adp + j);
        s1 += hv.x * av.x + hv.y * av.y + hv.z * av.z + hv.w * av.w;
        s2 += hv.x * dv.x + hv.y * dv.y + hv.z * dv.z + hv.w * dv.w;
    }
    s1 += __shfl_xor_sync(0xffffffff, s1, 1);
    s2 += __shfl_xor_sync(0xffffffff, s2, 1);
    s1 += __shfl_xor_sync(0xffffffff, s1, 2);
    s2 += __shfl_xor_sync(0xffffffff, s2, 2);
    if (q == 0) {
        es[row] = s1;
        ed[row] = s2;
    }
}

// ---------------- fused softmax + aggregation (warp per node, fp16 gather) ---
template<int H, bool ELU>
__global__ void __launch_bounds__(256) node_aggr(
    const int* __restrict__ off, const int* __restrict__ adj,
    const float* __restrict__ es, const float* __restrict__ ed,
    const __half* __restrict__ hfeat, const float* __restrict__ bias,
    float* __restrict__ out)
{
    constexpr int HD  = H * 64;
    constexpr int PER = HD / 32;          // 8 (H=4) or 2 (H=1)
    int node = blockIdx.x * 8 + (threadIdx.x >> 5);
    if (node >= NN) return;
    int lane = threadIdx.x & 31;
    int base = lane * PER;
    int head = base >> 6;

    float edv = ed[node * H + head];
    int e0 = off[node], e1 = off[node + 1];

    float acc[PER];
    #pragma unroll
    for (int j = 0; j < PER; j++) acc[j] = 0.0f;
    float denom = 0.0f;

    auto body = [&](int s, float x) {
        const __half* hp = hfeat + (size_t)s * HD + base;
        if constexpr (PER == 8) {
            uint4 raw = *reinterpret_cast<const uint4*>(hp);
            __half2 p0 = *reinterpret_cast<__half2*>(&raw.x);
            __half2 p1 = *reinterpret_cast<__half2*>(&raw.y);
            __half2 p2 = *reinterpret_cast<__half2*>(&raw.z);
            __half2 p3 = *reinterpret_cast<__half2*>(&raw.w);
            float2 f0 = __half22float2(p0), f1 = __half22float2(p1);
            float2 f2 = __half22float2(p2), f3 = __half22float2(p3);
            acc[0] += x * f0.x; acc[1] += x * f0.y;
            acc[2] += x * f1.x; acc[3] += x * f1.y;
            acc[4] += x * f2.x; acc[5] += x * f2.y;
            acc[6] += x * f3.x; acc[7] += x * f3.y;
        } else {
            __half2 p = *reinterpret_cast<const __half2*>(hp);
            float2 f = __half22float2(p);
            acc[0] += x * f.x; acc[1] += x * f.y;
        }
    };

    int e = e0;
    for (; e + 4 <= e1; e += 4) {
        int s0 = adj[e],     s1 = adj[e + 1];
        int s2 = adj[e + 2], s3 = adj[e + 3];
        float v0 = es[s0 * H + head] + edv;
        float v1 = es[s1 * H + head] + edv;
        float v2 = es[s2 * H + head] + edv;
        float v3 = es[s3 * H + head] + edv;
        v0 = (v0 > 0.0f) ? v0 : NEG_SLOPE * v0;
        v1 = (v1 > 0.0f) ? v1 : NEG_SLOPE * v1;
        v2 = (v2 > 0.0f) ? v2 : NEG_SLOPE * v2;
        v3 = (v3 > 0.0f) ? v3 : NEG_SLOPE * v3;
        float x0 = __expf(v0), x1 = __expf(v1);
        float x2 = __expf(v2), x3 = __expf(v3);
        denom += (x0 + x1) + (x2 + x3);
        body(s0, x0); body(s1, x1); body(s2, x2); body(s3, x3);
    }
    for (; e < e1; e++) {
        int s0 = adj[e];
        float v0 = es[s0 * H + head] + edv;
        v0 = (v0 > 0.0f) ? v0 : NEG_SLOPE * v0;
        float x0 = __expf(v0);
        denom += x0;
        body(s0, x0);
    }

    float inv = 1.0f / (denom + 1e-16f);
    float* op = out + (size_t)node * HD + base;
    float res[PER];
    #pragma unroll
    for (int j = 0; j < PER; j++) {
        float r = acc[j] * inv + bias[base + j];
        if (ELU) r = (r > 0.0f) ? r : expm1f(r);
        res[j] = r;
    }
    if constexpr (PER == 8) {
        *reinterpret_cast<float4*>(op)     = make_float4(res[0], res[1], res[2], res[3]);
        *reinterpret_cast<float4*>(op + 4) = make_float4(res[4], res[5], res[6], res[7]);
    } else {
        *reinterpret_cast<float2*>(op) = make_float2(res[0], res[1]);
    }
}

// ---------------- driver -----------------------------------------------------
extern "C" void kernel_launch(void* const* d_in, const int* in_sizes, int n_in,
                              void* d_out, int out_size)
{
    const float* x   = (const float*)d_in[0];
    const int*   ei  = (const int*)  d_in[1];
    const int*   src = ei;
    const int*   dst = ei + NE;
    const float* W1  = (const float*)d_in[2];
    const float* as1 = (const float*)d_in[3];
    const float* ad1 = (const float*)d_in[4];
    const float* b1  = (const float*)d_in[5];
    const float* W2  = (const float*)d_in[6];
    const float* as2 = (const float*)d_in[7];
    const float* ad2 = (const float*)d_in[8];
    const float* b2  = (const float*)d_in[9];
    const float* W3  = (const float*)d_in[10];
    const float* as3 = (const float*)d_in[11];
    const float* ad3 = (const float*)d_in[12];
    const float* b3  = (const float*)d_in[13];

    float *bufA, *bufB, *es, *ed;
    __half* bufH;
    int *deg, *off, *cursor, *adj;
    cudaGetSymbolAddress((void**)&bufA, g_bufA);
    cudaGetSymbolAddress((void**)&bufB, g_bufB);
    cudaGetSymbolAddress((void**)&bufH, g_bufH);
    cudaGetSymbolAddress((void**)&es,   g_es);
    cudaGetSymbolAddress((void**)&ed,   g_ed);
    cudaGetSymbolAddress((void**)&deg,    g_deg);
    cudaGetSymbolAddress((void**)&off,    g_off);
    cudaGetSymbolAddress((void**)&cursor, g_cursor);
    cudaGetSymbolAddress((void**)&adj,    g_adj);

    cudaFuncSetAttribute(gemm_tf32,
                         cudaFuncAttributeMaxDynamicSharedMemorySize, GEMM_SMEM);

    const int TB = 256;
    const int eblk  = (NE + TB - 1) / TB;
    const int mblk  = (NN + 127) / 128;
    const int nblk  = (NN + 7) / 8;            // warp per node
    const int awrp4 = ((NN * 4 + 7) / 8 + 7) / 8;
    const int awrp1 = ((NN + 7) / 8 + 7) / 8;

    // ---- CSR build (once) ----
    cudaMemsetAsync(deg, 0, NN * sizeof(int));
    count_deg<<<eblk, TB>>>(dst, deg);
    scan_offsets<<<1, 1024>>>(deg, off, cursor);
    fill_adj<<<eblk, TB>>>(src, dst, cursor, adj);

    // ---- layer 1 (H=4) ----
    gemm_tf32<<<dim3(2, mblk), TB, GEMM_SMEM>>>(x, W1, bufA, bufH, NN, 256, 256);
    attn_coef<4><<<awrp4, TB>>>(bufA, as1, ad1, es, ed);
    node_aggr<4, true><<<nblk, TB>>>(off, adj, es, ed, bufH, b1, bufB);

    // ---- layer 2 (H=4) ----
    gemm_tf32<<<dim3(2, mblk), TB, GEMM_SMEM>>>(bufB, W2, bufA, bufH, NN, 256, 256);
    attn_coef<4><<<awrp4, TB>>>(bufA, as2, ad2, es, ed);
    node_aggr<4, true><<<nblk, TB>>>(off, adj, es, ed, bufH, b2, bufB);

    // ---- layer 3 (H=1) ----
    float* outp = (float*)d_out;
    gemm_tf32<<<dim3(1, mblk), TB, GEMM_SMEM>>>(bufB, W3, bufA, bufH, NN, 64, 256);
    attn_coef<1><<<awrp1, TB>>>(bufA, as3, ad3, es, ed);
    node_aggr<1, false><<<nblk, TB>>>(off, adj, es, ed, bufH, b3, outp);
}